// round 11
// baseline (speedup 1.0000x reference)
#include <cuda_runtime.h>
#include <cstdint>

// predictions [8,19,512,1024] f32, targets [8,512,1024] i32, output: scalar f32.
#define NB        8
#define NC        19
#define NPB       (512 * 1024)
#define THRESH    0.7f
#define NMIN      10000

#define TPB       256
#define WARPS     (TPB / 32)
#define TILE_P    64                       // pixels per warp-tile (2 px / lane)
#define ROW_B     (TILE_P * 4)             // 256 B per channel row
#define W_BYTES   ((NC + 1) * ROW_B)       // 5120 B per warp-tile
#define STAGES    2
#define BLK_PER_BATCH 37
#define GRID      (NB * BLK_PER_BATCH)     // 296 (2 blocks/SM)
#define WPBW      (BLK_PER_BATCH * WARPS)  // 296 warps per batch
#define TILES_PB  (NPB / TILE_P)           // 8192 warp-tiles per batch

__device__ double       g_sum[NB];
__device__ int          g_cnt[NB];
__device__ unsigned int g_done;

// ---------------- PTX helpers ----------------
__device__ __forceinline__ uint32_t smem_u32(const void* p) {
    uint32_t a;
    asm("{ .reg .u64 t; cvta.to.shared.u64 t, %1; cvt.u32.u64 %0, t; }"
        : "=r"(a) : "l"(p));
    return a;
}
#define MBAR_INIT(addr, cnt) \
    asm volatile("mbarrier.init.shared.b64 [%0], %1;" :: "r"(addr), "r"(cnt) : "memory")
#define MBAR_EXPECT_TX(addr, bytes) \
    asm volatile("mbarrier.arrive.expect_tx.shared.b64 _, [%0], %1;" :: "r"(addr), "r"(bytes) : "memory")
#define MBAR_WAIT(addr, parity) do {                                              \
    asm volatile("{\n\t.reg .pred P;\n"                                           \
                 "W_%=:\n\t"                                                      \
                 "mbarrier.try_wait.parity.acquire.cta.shared::cta.b64 P, [%0], %1, 0x989680;\n\t" \
                 "@P bra D_%=;\n\t"                                               \
                 "bra W_%=;\n"                                                    \
                 "D_%=:\n\t}"                                                     \
                 :: "r"(addr), "r"(parity) : "memory");                           \
} while (0)
#define TMA_BULK_G2S(dst, src, bytes, mbar) \
    asm volatile("cp.async.bulk.shared::cta.global.mbarrier::complete_tx::bytes [%0], [%1], %2, [%3];" \
                 :: "r"(dst), "l"(src), "r"(bytes), "r"(mbar) : "memory")
#define FENCE_ASYNC() \
    asm volatile("fence.proxy.async.shared::cta;" ::: "memory")

// CE loss recompute, exact f32 (rare exact-top-k fallback path only).
__device__ __forceinline__ float pixel_loss(const float* __restrict__ pred,
                                            const int*   __restrict__ tgt,
                                            int b, int i) {
    const int t = tgt[b * NPB + i];
    float s = 0.f, xt = 0.f;
#pragma unroll
    for (int c = 0; c < NC; c++) {
        const float v = pred[(b * NC + c) * NPB + i];
        s += __expf(v);
        if (c == t) xt = v;
    }
    float l = __logf(s) - xt;
    return l < 0.f ? 0.f : l;
}

extern __shared__ float sbuf[];   // WARPS * STAGES * W_BYTES, 16B aligned

// Lane 0 of the warp issues 20 bulk copies (one per 256B row) for one tile.
// ~25 issue slots per 5120B tile instead of 320 LDGSTS -> LSU accept-rate
// bottleneck removed; the TMA engine injects DRAM requests at the LTS cap.
__device__ __forceinline__ void fill_tile_tma(const float* __restrict__ pred,
                                              const int*   __restrict__ tgt,
                                              uint32_t dst, uint32_t mbar,
                                              int b, int n, int lane) {
    if (lane == 0) {
        MBAR_EXPECT_TX(mbar, W_BYTES);
        const char* pb = (const char*)(pred + (size_t)b * NC * NPB + n);
#pragma unroll
        for (int c = 0; c < NC; c++)
            TMA_BULK_G2S(dst + c * ROW_B, pb + (size_t)c * NPB * 4, ROW_B, mbar);
        TMA_BULK_G2S(dst + NC * ROW_B,
                     (const char*)(tgt + (size_t)b * NPB + n), ROW_B, mbar);
    }
}

__global__ void __launch_bounds__(TPB)
ohem_tmaw(const float* __restrict__ pred,
          const int*   __restrict__ tgt,
          float*       __restrict__ out) {
    __shared__ __align__(8) uint64_t mbar[WARPS * STAGES];
    __shared__ float        sh_f[WARPS];
    __shared__ int          sh_i[WARPS];
    __shared__ unsigned int sh_last;

    const int tid  = threadIdx.x;
    const int wid  = tid >> 5, lane = tid & 31;
    const uint32_t sb = smem_u32(sbuf);
    const uint32_t mb = smem_u32(mbar);

    if (tid < WARPS * STAGES) MBAR_INIT(mb + tid * 8, 1);
    __syncthreads();

    // Block -> (batch, warp-in-batch). 296 = 8 * 37 keeps batch block-pure.
    const int b  = blockIdx.x / BLK_PER_BATCH;
    const int jb = blockIdx.x % BLK_PER_BATCH;
    const int wb = jb * WARPS + wid;           // 0..295 within batch
    const int ntiles = (TILES_PB - wb + WPBW - 1) / WPBW;   // >= 27

    const uint32_t wbase = sb + wid * (STAGES * W_BYTES);
    const uint32_t wmbar = mb + wid * (STAGES * 8);

    // Prologue: fill both stages (warp-private, no block sync).
#pragma unroll
    for (int s = 0; s < STAGES; s++)
        fill_tile_tma(pred, tgt, wbase + s * W_BYTES, wmbar + s * 8,
                      b, (wb + s * WPBW) * TILE_P, lane);

    float ls = 0.f;
    int   lc = 0;

    for (int k = 0; k < ntiles; k++) {
        const int stage  = k & (STAGES - 1);
        const int parity = (k >> 1) & 1;
        MBAR_WAIT(wmbar + stage * 8, parity);

        const float*  buf = sbuf + (wid * STAGES + stage) * (W_BYTES / 4);
        const float2* bp  = reinterpret_cast<const float2*>(buf);

        float s0 = 0.f, s1 = 0.f;
#pragma unroll
        for (int c = 0; c < NC; c++) {
            const float2 v = bp[c * 32 + lane];
            s0 += __expf(v.x);
            s1 += __expf(v.y);
        }
        const int2 tt = reinterpret_cast<const int2*>(buf + NC * TILE_P)[lane];
        const float l0 = __logf(s0) - buf[tt.x * TILE_P + 2 * lane];
        const float l1 = __logf(s1) - buf[tt.y * TILE_P + 2 * lane + 1];
        if (l0 > THRESH) { ls += l0; lc++; }
        if (l1 > THRESH) { ls += l1; lc++; }

        __syncwarp();            // all lanes done reading this stage
        if (k + STAGES < ntiles) {
            FENCE_ASYNC();       // order generic reads before async refill
            fill_tile_tma(pred, tgt, wbase + stage * W_BYTES, wmbar + stage * 8,
                          b, (wb + (k + STAGES) * WPBW) * TILE_P, lane);
        }
    }

    // Single block reduction + one atomic pair at the very end.
#pragma unroll
    for (int o = 16; o; o >>= 1) {
        ls += __shfl_down_sync(0xffffffffu, ls, o);
        lc += __shfl_down_sync(0xffffffffu, lc, o);
    }
    if (lane == 0) { sh_f[wid] = ls; sh_i[wid] = lc; }
    __syncthreads();
    if (tid == 0) {
        double S = 0.0; int Cn = 0;
#pragma unroll
        for (int i = 0; i < WARPS; i++) { S += (double)sh_f[i]; Cn += sh_i[i]; }
        atomicAdd(&g_sum[b], S);
        atomicAdd(&g_cnt[b], Cn);
        __threadfence();
        const unsigned int tk = atomicAdd(&g_done, 1u);
        sh_last = (tk == (unsigned)(GRID - 1)) ? 1u : 0u;
    }
    __syncthreads();
    if (!sh_last) return;

    // ---------------- finalize (last block) --------------------------------
    __threadfence();

    __shared__ unsigned int hist[256];
    __shared__ unsigned int s_prefix;
    __shared__ int          s_k;
    __shared__ double       sh_d2[WARPS];
    __shared__ int          sh_i2[WARPS];
    __shared__ double       s_acc;

    if (tid == 0) s_acc = 0.0;
    __syncthreads();

    for (int bb = 0; bb < NB; bb++) {
        const int    cnt = g_cnt[bb];
        const double sum = g_sum[bb];

        if (cnt >= NMIN) {
            if (tid == 0) s_acc += sum / (double)cnt;
            __syncthreads();
        } else {
            // Exact top-NMIN via 4-pass MSB radix select (dead on this input).
            if (tid == 0) { s_prefix = 0u; s_k = NMIN; }
            __syncthreads();
            for (int pass = 0; pass < 4; pass++) {
                const int shift = 24 - pass * 8;
                for (int i = tid; i < 256; i += TPB) hist[i] = 0u;
                __syncthreads();
                const unsigned prefix  = s_prefix;
                const unsigned mask_hi = (pass == 0) ? 0u
                                       : (0xFFFFFFFFu << (shift + 8));
                for (int i = tid; i < NPB; i += TPB) {
                    const unsigned u = __float_as_uint(pixel_loss(pred, tgt, bb, i));
                    if ((u & mask_hi) == prefix)
                        atomicAdd(&hist[(u >> shift) & 255u], 1u);
                }
                __syncthreads();
                if (tid == 0) {
                    int kk = s_k;
                    int d  = 255;
                    while (d > 0 && (int)hist[d] < kk) { kk -= (int)hist[d]; d--; }
                    s_prefix = prefix | ((unsigned)d << shift);
                    s_k      = kk;
                }
                __syncthreads();
            }
            const float pivot = __uint_as_float(s_prefix);
            double fs = 0.0; int fg = 0;
            for (int i = tid; i < NPB; i += TPB) {
                const float vv = pixel_loss(pred, tgt, bb, i);
                if (vv > pivot) { fs += (double)vv; fg++; }
            }
#pragma unroll
            for (int o = 16; o; o >>= 1) {
                fs += __shfl_down_sync(0xffffffffu, fs, o);
                fg += __shfl_down_sync(0xffffffffu, fg, o);
            }
            if (lane == 0) { sh_d2[wid] = fs; sh_i2[wid] = fg; }
            __syncthreads();
            if (tid == 0) {
                double S = 0.0; int G = 0;
#pragma unroll
                for (int i = 0; i < WARPS; i++) { S += sh_d2[i]; G += sh_i2[i]; }
                const double kept = S + (double)(NMIN - G) * (double)pivot;
                s_acc += kept / (double)NMIN;
            }
            __syncthreads();
        }
    }

    if (tid == 0) {
        out[0] = (float)(s_acc / (double)NB);
#pragma unroll
        for (int i = 0; i < NB; i++) { g_sum[i] = 0.0; g_cnt[i] = 0; }
        g_done = 0u;
        __threadfence();
    }
}

extern "C" void kernel_launch(void* const* d_in, const int* in_sizes, int n_in,
                              void* d_out, int out_size) {
    const float* pred = (const float*)d_in[0];
    const int*   tgt  = (const int*)d_in[1];
    float*       out  = (float*)d_out;

    static int smem_set = 0;
    if (!smem_set) {
        cudaFuncSetAttribute(ohem_tmaw,
                             cudaFuncAttributeMaxDynamicSharedMemorySize,
                             WARPS * STAGES * W_BYTES);
        smem_set = 1;
    }
    ohem_tmaw<<<GRID, TPB, WARPS * STAGES * W_BYTES>>>(pred, tgt, out);
}